// round 8
// baseline (speedup 1.0000x reference)
#include <cuda_runtime.h>
#include <math.h>

#define B_  32
#define T_  20
#define C_  512
#define P_  196
#define H_  1024
#define NC_ 101
#define NBLK 148
#define NTHR 512
#define NWRP 16

#define SMEM_FLOATS (16 * 1024 + 64)
#define SMEM_BYTES (SMEM_FLOATS * 4)

// ---------------- device scratch ----------------
__device__ float g_sA2pre[T_ * B_ * P_];
__device__ float g_tC2pre[T_ * B_ * P_];
__device__ float g_scT[200 * B_];         // scores [row][b]; row 196 = h2.W_h21
__device__ float g_YT[C_ * B_];           // [c][b]
__device__ float g_h1T[2][H_ * B_];       // [h][b] double-buffered by step parity
__device__ float g_h2T[2][H_ * B_];
__device__ float g_h2hist[T_ * H_ * B_];
__device__ float g_c1[H_ * B_];
__device__ float g_c2[H_ * B_];
__device__ float g_beta[T_ * B_];
__device__ float g_betasT[B_ * T_];
__device__ float g_hbarN[B_ * H_];
__device__ unsigned g_cnt2[32 * 32];      // 32 padded arrival counters (self-resetting)
__device__ volatile unsigned g_bar_gen;

__device__ __forceinline__ float sigm(float x) { return 1.0f / (1.0f + __expf(-x)); }
__device__ __forceinline__ float ftanh(float x) { return 1.0f - 2.0f / (__expf(2.0f * x) + 1.0f); }
__device__ __forceinline__ float d4(float4 a, float4 b) {
    return a.x * b.x + a.y * b.y + a.z * b.z + a.w * b.w;
}

// packed fp32x2
__device__ __forceinline__ unsigned long long splat2(float w) {
    unsigned long long d; unsigned u = __float_as_uint(w);
    asm("mov.b64 %0, {%1, %1};" : "=l"(d) : "r"(u));
    return d;
}
__device__ __forceinline__ unsigned long long fma2(unsigned long long a, unsigned long long b,
                                                   unsigned long long c) {
    unsigned long long d;
    asm("fma.rn.f32x2 %0, %1, %2, %3;" : "=l"(d) : "l"(a), "l"(b), "l"(c));
    return d;
}

// distributed grid barrier: 32 counters; block0 warp detects + resets + releases.
// Replay-safe: counters self-reset to 0 every barrier; gen compared relative to gen0.
__device__ __forceinline__ void grid_sync(unsigned& barI, unsigned gen0) {
    barI++;
    __syncthreads();
    const int tid = threadIdx.x, bid = blockIdx.x;
    if (tid == 0) { __threadfence(); atomicAdd(&g_cnt2[(bid & 31) * 32], 1u); }
    if (bid == 0 && tid < 32) {
        unsigned nj = (tid < 20) ? 5u : 4u;
        volatile unsigned* c = &g_cnt2[tid * 32];
        while (*c < nj) __nanosleep(32);
        atomicSub(&g_cnt2[tid * 32], nj);
        __syncwarp(0xffffffffu);
        if (tid == 0) { __threadfence(); g_bar_gen = gen0 + barI; }
    } else if (tid == 0) {
        while ((unsigned)(g_bar_gen - gen0) < barI) __nanosleep(32);
    }
    __threadfence();
    __syncthreads();
}

// ---------------- LSTM: all-LDG f32x2 GEMM + fused cell ----------------
// 128 blocks: 8 h-units (32 gate-rows) x 32 batch. 16 warps = private k-slices.
// Thread: 4 gate-rows (8i+trow) x 8 batches (tx*8..+7). No smem in mainloop.
template <int MODE>
__device__ void lstm_phase(int t,
                           const float* __restrict__ Wih, const float* __restrict__ Whh,
                           const float* __restrict__ bih, const float* __restrict__ bhh,
                           float* dsm) {
    constexpr int K1 = (MODE == 0) ? C_ : H_;
    constexpr int K = K1 + H_;
    constexpr int KG = K / 16;
    const int bid = blockIdx.x, tid = threadIdx.x;
    if (bid < 128) {
        const float* __restrict__ X1 = (MODE == 0) ? g_YT : g_h1T[(t + 1) & 1];
        const float* __restrict__ X2 = (MODE == 0) ? g_h1T[t & 1] : g_h2T[t & 1];
        const int h0 = bid * 8;
        const int g = tid >> 5, lane = tid & 31;
        const int trow = lane >> 2;      // unit 0..7
        const int tx = lane & 3;         // batch oct

        unsigned long long acc[4][4];
#pragma unroll
        for (int i = 0; i < 4; i++)
#pragma unroll
            for (int j = 0; j < 4; j++) acc[i][j] = 0ull;

        const int kbase = g * KG;
#pragma unroll 2
        for (int k = 0; k < KG; k += 4) {
            const int kg2 = kbase + k;
            const bool first = (kg2 < K1);
            float4 wq[4];
#pragma unroll
            for (int i = 0; i < 4; i++) {
                const size_t grow = (size_t)(i * H_ + h0 + trow);
                const float* src = first ? (Wih + grow * K1 + kg2)
                                         : (Whh + grow * H_ + (kg2 - K1));
                wq[i] = *(const float4*)src;
            }
            ulonglong2 xlo[4], xhi[4];
#pragma unroll
            for (int r = 0; r < 4; r++) {
                const float* xs = first ? (X1 + (kg2 + r) * B_) : (X2 + (kg2 + r - K1) * B_);
                xlo[r] = *(const ulonglong2*)(xs + tx * 8);
                xhi[r] = *(const ulonglong2*)(xs + tx * 8 + 4);
            }
#pragma unroll
            for (int r = 0; r < 4; r++) {
#pragma unroll
                for (int i = 0; i < 4; i++) {
                    unsigned long long w2 = splat2(((const float*)&wq[i])[r]);
                    acc[i][0] = fma2(w2, xlo[r].x, acc[i][0]);
                    acc[i][1] = fma2(w2, xlo[r].y, acc[i][1]);
                    acc[i][2] = fma2(w2, xhi[r].x, acc[i][2]);
                    acc[i][3] = fma2(w2, xhi[r].y, acc[i][3]);
                }
            }
        }

        // partials: Gs[16][32 rows][32 b]
        float* Gs = dsm;
#pragma unroll
        for (int i = 0; i < 4; i++) {
            ulonglong2 u0; u0.x = acc[i][0]; u0.y = acc[i][1];
            ulonglong2 u1; u1.x = acc[i][2]; u1.y = acc[i][3];
            *(ulonglong2*)&Gs[g * 1024 + (8 * i + trow) * 32 + tx * 8]     = u0;
            *(ulonglong2*)&Gs[g * 1024 + (8 * i + trow) * 32 + tx * 8 + 4] = u1;
        }
        __syncthreads();

        if (tid < 256) {
            int u = tid >> 5, b = tid & 31;
            float gate[4];
#pragma unroll
            for (int q = 0; q < 4; q++) {
                int l = q * 8 + u;
                int row = q * H_ + h0 + u;
                float s = bih[row] + bhh[row];
#pragma unroll
                for (int gg = 0; gg < 16; gg++) s += Gs[gg * 1024 + l * 32 + b];
                gate[q] = s;
            }
            float i_ = sigm(gate[0]), f_ = sigm(gate[1]), gv = ftanh(gate[2]), o_ = sigm(gate[3]);
            float* cS = (MODE == 0) ? g_c1 : g_c2;
            int hb = (h0 + u) * B_ + b;
            float cn = f_ * cS[hb] + i_ * gv;
            float hn = o_ * ftanh(cn);
            cS[hb] = cn;
            if (MODE == 0) {
                g_h1T[(t + 1) & 1][hb] = hn;
            } else {
                g_h2T[(t + 1) & 1][hb] = hn;
                g_h2hist[(size_t)t * H_ * B_ + hb] = hn;
            }
        }
        __syncthreads();
    }
}

// ---------------- the single persistent kernel ----------------
__global__ void __launch_bounds__(NTHR, 1)
stdec_kernel(const float* __restrict__ videos,
             const float* __restrict__ h1in, const float* __restrict__ c1in,
             const float* __restrict__ h2in, const float* __restrict__ c2in,
             const float* __restrict__ spatialBias, const float* __restrict__ temporalBias,
             const float* __restrict__ W_h2p, const float* __restrict__ b_h2p,
             const float* __restrict__ W_sC21, const float* __restrict__ b_sC21,
             const float* __restrict__ W_h21, const float* __restrict__ b_h21,
             const float* __restrict__ W_tC21, const float* __restrict__ b_tC21,
             const float* __restrict__ Wih1, const float* __restrict__ Whh1,
             const float* __restrict__ bih1, const float* __restrict__ bhh1,
             const float* __restrict__ Wih2, const float* __restrict__ Whh2,
             const float* __restrict__ bih2, const float* __restrict__ bhh2,
             const float* __restrict__ W_fc, const float* __restrict__ b_fc,
             float* __restrict__ logits_out, float* __restrict__ alphas_out,
             float* __restrict__ betasT_out) {
    extern __shared__ __align__(16) float dsm[];
    const int bid = blockIdx.x, tid = threadIdx.x;
    const int lane = tid & 31, wid = tid >> 5;
    const int gw = bid * NWRP + wid;

    unsigned barI = 0;
    unsigned gen0 = g_bar_gen;   // captured before any barrier of this launch

    // ---- init states ----
    for (int idx = bid * NTHR + tid; idx < H_ * B_; idx += NBLK * NTHR) {
        int h = idx >> 5;
        g_h1T[0][idx] = h1in[h];
        g_h2T[0][idx] = h2in[h];
        g_c1[idx] = c1in[h];
        g_c2[idx] = c2in[h];
    }

    // ---- precompute sA2pre / tC2pre (2 tasks per block) ----
    {
        float* ws = dsm;
        float* wt = dsm + C_;
        for (int i = tid; i < C_; i += NTHR) { ws[i] = W_sC21[i]; wt[i] = W_tC21[i]; }
        __syncthreads();
        float bs0 = b_sC21[0];
        int half = tid >> 8, p = tid & 255;
        for (int task = bid * 2 + half; task < B_ * T_; task += NBLK * 2) {
            int b = task / T_, t = task % T_;
            if (p < P_) {
                const float* vp = videos + ((size_t)(b * T_ + t) * C_) * P_ + p;
                float accs = 0.f, acct = 0.f;
#pragma unroll 8
                for (int c = 0; c < C_; c++) {
                    float v = vp[(size_t)c * P_];
                    accs += v * ws[c];
                    acct += v * wt[c];
                }
                int o = (t * B_ + b) * P_ + p;
                g_sA2pre[o] = accs + bs0 + spatialBias[p];
                g_tC2pre[o] = acct;
            }
        }
        __syncthreads();
    }
    grid_sync(barI, gen0);

    // ---- recurrence: 4 phases / 4 barriers per step ----
    for (int t = 0; t < T_; t++) {
        // phase 1: scores GEMM  S[197,32] = [W_h2p;W_h21] @ h2T   (blocks 0..24)
        if (bid < 25) {
            const float* __restrict__ X = g_h2T[t & 1];
            const int r0 = bid * 8;
            const int g = wid;
            const int row = lane >> 2, tx = lane & 3;
            const int r = r0 + row;
            const float* wbase = (r < 196) ? (W_h2p + (size_t)r * H_) : W_h21;  // clamp
            unsigned long long acc[4] = {0ull, 0ull, 0ull, 0ull};
            const int KGs = H_ / 16;  // 64
            const int kbase = g * KGs;
#pragma unroll 2
            for (int k = 0; k < KGs; k += 4) {
                int kg2 = kbase + k;
                float4 w4 = *(const float4*)(wbase + kg2);
#pragma unroll
                for (int rr = 0; rr < 4; rr++) {
                    const float* xs = X + (kg2 + rr) * B_ + tx * 8;
                    ulonglong2 xl = *(const ulonglong2*)xs;
                    ulonglong2 xh = *(const ulonglong2*)(xs + 4);
                    unsigned long long w2 = splat2(((const float*)&w4)[rr]);
                    acc[0] = fma2(w2, xl.x, acc[0]);
                    acc[1] = fma2(w2, xl.y, acc[1]);
                    acc[2] = fma2(w2, xh.x, acc[2]);
                    acc[3] = fma2(w2, xh.y, acc[3]);
                }
            }
            float* Ss = dsm;  // [16][8][32]
            {
                ulonglong2 u0; u0.x = acc[0]; u0.y = acc[1];
                ulonglong2 u1; u1.x = acc[2]; u1.y = acc[3];
                *(ulonglong2*)&Ss[g * 256 + row * 32 + tx * 8]     = u0;
                *(ulonglong2*)&Ss[g * 256 + row * 32 + tx * 8 + 4] = u1;
            }
            __syncthreads();
            if (tid < 256) {
                int rr = tid >> 5, b = tid & 31;
                float s = 0.f;
#pragma unroll
                for (int gg = 0; gg < 16; gg++) s += Ss[gg * 256 + rr * 32 + b];
                int rg = r0 + rr;
                if (rg <= 196) g_scT[rg * 32 + b] = s;
            }
        }
        grid_sync(barI, gen0);

        // phase 2: softmax + alpha/beta out + Y (blocks 0..31, one per batch)
        if (bid < B_) {
            int b = bid;
            float* sred    = dsm;         // [16]
            float* s_alpha = dsm + 16;    // [196]

            float v = -1e30f;
            if (tid < P_) v = g_scT[tid * 32 + b] + b_h2p[tid] + g_sA2pre[(t * B_ + b) * P_ + tid];
            float m = v;
            for (int o = 16; o; o >>= 1) m = fmaxf(m, __shfl_xor_sync(~0u, m, o));
            if (lane == 0) sred[wid] = m;
            __syncthreads();
            float mAll = sred[0];
#pragma unroll
            for (int i = 1; i < NWRP; i++) mAll = fmaxf(mAll, sred[i]);
            float e = (tid < P_) ? __expf(v - mAll) : 0.f;
            float s = e;
            for (int o = 16; o; o >>= 1) s += __shfl_xor_sync(~0u, s, o);
            __syncthreads();
            if (lane == 0) sred[wid] = s;
            __syncthreads();
            float sAll = sred[0];
#pragma unroll
            for (int i = 1; i < NWRP; i++) sAll += sred[i];
            float a = e / sAll;
            __syncthreads();
            if (tid < P_) {
                s_alpha[tid] = a;
                alphas_out[((size_t)t * B_ + b) * P_ + tid] = a;
            }
            __syncthreads();

            // beta
            {
                float acc = (tid < P_) ? a * g_tC2pre[(t * B_ + b) * P_ + tid] : 0.f;
                for (int o = 16; o; o >>= 1) acc += __shfl_xor_sync(~0u, acc, o);
                if (lane == 0) sred[wid] = acc;
                __syncthreads();
                if (tid == 0) {
                    float sum = 0.f;
#pragma unroll
                    for (int i = 0; i < NWRP; i++) sum += sred[i];
                    g_beta[t * B_ + b] = sum + g_scT[196 * 32 + b] + b_h21[0] + b_tC21[0] + temporalBias[0];
                }
            }

            // Y: warp per c
            for (int c = wid; c < C_; c += NWRP) {
                const float* vp = videos + (((size_t)b * T_ + t) * C_ + c) * P_;
                float acc = 0.f;
                for (int p = lane; p < P_; p += 32) acc += s_alpha[p] * vp[p];
                for (int o = 16; o; o >>= 1) acc += __shfl_xor_sync(~0u, acc, o);
                if (lane == 0) g_YT[c * B_ + b] = acc;
            }
        }
        grid_sync(barI, gen0);

        lstm_phase<0>(t, Wih1, Whh1, bih1, bhh1, dsm);
        grid_sync(barI, gen0);
        lstm_phase<1>(t, Wih2, Whh2, bih2, bhh2, dsm);
        grid_sync(barI, gen0);
    }

    // ---- betas softmax over time ----
    if (bid == 0 && tid < B_) {
        int b = tid;
        float v[T_];
        float m = -1e30f;
#pragma unroll
        for (int t = 0; t < T_; t++) { v[t] = g_beta[t * B_ + b]; m = fmaxf(m, v[t]); }
        float s = 0.f;
#pragma unroll
        for (int t = 0; t < T_; t++) { v[t] = __expf(v[t] - m); s += v[t]; }
        float inv = 1.f / s;
#pragma unroll
        for (int t = 0; t < T_; t++) {
            float bt = v[t] * inv;
            g_betasT[b * T_ + t] = bt;
            betasT_out[b * T_ + t] = bt;
        }
    }
    grid_sync(barI, gen0);

    // ---- hbar[b][h] = sum_t betasT[b][t] * h2hist[t][h][b] ----
    for (int idx = bid * NTHR + tid; idx < H_ * B_; idx += NBLK * NTHR) {
        int h = idx >> 5, b = idx & 31;
        float acc = 0.f;
#pragma unroll
        for (int t = 0; t < T_; t++)
            acc += g_betasT[b * T_ + t] * g_h2hist[(size_t)t * H_ * B_ + h * B_ + b];
        g_hbarN[b * H_ + h] = acc;
    }
    grid_sync(barI, gen0);

    // ---- logits ----
    for (int task = gw; task < NC_ * B_; task += NBLK * NWRP) {
        int nc = task / B_, b = task % B_;
        const float4* wr = (const float4*)(W_fc + (size_t)nc * H_);
        const float4* xr = (const float4*)(g_hbarN + (size_t)b * H_);
        float acc = 0.f;
#pragma unroll
        for (int j = 0; j < 8; j++) acc += d4(wr[lane + 32 * j], xr[lane + 32 * j]);
        for (int o = 16; o; o >>= 1) acc += __shfl_xor_sync(~0u, acc, o);
        if (lane == 0) logits_out[b * NC_ + nc] = acc + b_fc[nc];
    }
}

// ---------------- launch ----------------
extern "C" void kernel_launch(void* const* d_in, const int* in_sizes, int n_in,
                              void* d_out, int out_size) {
    const float* videos       = (const float*)d_in[0];
    const float* h1           = (const float*)d_in[1];
    const float* c1           = (const float*)d_in[2];
    const float* h2           = (const float*)d_in[3];
    const float* c2           = (const float*)d_in[4];
    const float* spatialBias  = (const float*)d_in[5];
    const float* temporalBias = (const float*)d_in[6];
    const float* W_h2p        = (const float*)d_in[7];
    const float* b_h2p        = (const float*)d_in[8];
    const float* W_sC21       = (const float*)d_in[9];
    const float* b_sC21       = (const float*)d_in[10];
    const float* W_h21        = (const float*)d_in[11];
    const float* b_h21        = (const float*)d_in[12];
    const float* W_tC21       = (const float*)d_in[13];
    const float* b_tC21       = (const float*)d_in[14];
    const float* Wih1         = (const float*)d_in[15];
    const float* Whh1         = (const float*)d_in[16];
    const float* bih1         = (const float*)d_in[17];
    const float* bhh1         = (const float*)d_in[18];
    const float* Wih2         = (const float*)d_in[19];
    const float* Whh2         = (const float*)d_in[20];
    const float* bih2         = (const float*)d_in[21];
    const float* bhh2         = (const float*)d_in[22];
    const float* W_fc         = (const float*)d_in[23];
    const float* b_fc         = (const float*)d_in[24];

    float* out        = (float*)d_out;
    float* logits_out = out;
    float* alphas_out = out + B_ * NC_;
    float* betasT_out = out + B_ * NC_ + (size_t)T_ * B_ * P_;

    cudaFuncSetAttribute(stdec_kernel, cudaFuncAttributeMaxDynamicSharedMemorySize, SMEM_BYTES);
    stdec_kernel<<<NBLK, NTHR, SMEM_BYTES>>>(videos, h1, c1, h2, c2, spatialBias, temporalBias,
                                 W_h2p, b_h2p, W_sC21, b_sC21, W_h21, b_h21, W_tC21, b_tC21,
                                 Wih1, Whh1, bih1, bhh1, Wih2, Whh2, bih2, bhh2,
                                 W_fc, b_fc, logits_out, alphas_out, betasT_out);
}

// round 9
// speedup vs baseline: 2.1022x; 2.1022x over previous
#include <cuda_runtime.h>
#include <math.h>

#define B_  32
#define T_  20
#define C_  512
#define P_  196
#define H_  1024
#define NC_ 101
#define NBLK 148
#define NTHR 512
#define NWRP 16

// LSTM tiling: 16 k-groups (1 warp each), chunk = 16 k, triple-buffered
#define NGRP 16
#define CHK 16
#define XSTR 32                       // X tile row stride: [16 k][32 b]
#define WSTR 20                       // W tile row stride: [32 rows][16 k pad 20]
#define XSZ (CHK * XSTR)              // 512
#define WSZ (32 * WSTR)               // 640
#define GRPSZ (XSZ + WSZ)             // 1152
#define NBUF 3
#define SMEM_FLOATS (NBUF * NGRP * GRPSZ)   // 55296 floats = 221184 B
#define SMEM_BYTES (SMEM_FLOATS * 4)

// ---------------- device scratch ----------------
__device__ float g_sA2pre[T_ * B_ * P_];
__device__ float g_tC2pre[T_ * B_ * P_];
__device__ float g_sc[B_ * P_];
__device__ float g_betaH[B_];
__device__ float g_YT[C_ * B_];           // [c][b]
__device__ float g_h1T[2][H_ * B_];       // [h][b] double-buffered by step parity
__device__ float g_h2T[2][H_ * B_];
__device__ float g_h2n[B_ * H_];          // [b][h] copy for attention dots
__device__ float g_h2hist[T_ * H_ * B_];
__device__ float g_c1[H_ * B_];
__device__ float g_c2[H_ * B_];
__device__ float g_beta[T_ * B_];
__device__ float g_betasT[B_ * T_];
__device__ float g_hbarN[B_ * H_];
__device__ unsigned g_cnt2[32 * 32];      // 32 padded arrival counters (self-resetting)
__device__ volatile unsigned g_bar_gen;

__device__ __forceinline__ float sigm(float x) { return 1.0f / (1.0f + __expf(-x)); }
__device__ __forceinline__ float ftanh(float x) { return 1.0f - 2.0f / (__expf(2.0f * x) + 1.0f); }
__device__ __forceinline__ float d4(float4 a, float4 b) {
    return a.x * b.x + a.y * b.y + a.z * b.z + a.w * b.w;
}

// packed fp32x2 (full-rate fp32 on sm_103a)
__device__ __forceinline__ unsigned long long splat2(float w) {
    unsigned long long d; unsigned u = __float_as_uint(w);
    asm("mov.b64 %0, {%1, %1};" : "=l"(d) : "r"(u));
    return d;
}
__device__ __forceinline__ unsigned long long fma2(unsigned long long a, unsigned long long b,
                                                   unsigned long long c) {
    unsigned long long d;
    asm("fma.rn.f32x2 %0, %1, %2, %3;" : "=l"(d) : "l"(a), "l"(b), "l"(c));
    return d;
}

__device__ __forceinline__ void cp16(float* dst, const float* src) {
    unsigned u = (unsigned)__cvta_generic_to_shared(dst);
    asm volatile("cp.async.cg.shared.global [%0], [%1], 16;" :: "r"(u), "l"(src));
}
__device__ __forceinline__ void cp_commit() { asm volatile("cp.async.commit_group;" ::: "memory"); }
__device__ __forceinline__ void cp_wait2()  { asm volatile("cp.async.wait_group 2;" ::: "memory"); }
__device__ __forceinline__ void cp_wait1()  { asm volatile("cp.async.wait_group 1;" ::: "memory"); }
__device__ __forceinline__ void cp_wait0()  { asm volatile("cp.async.wait_group 0;" ::: "memory"); }

// distributed grid barrier: 32 counters; block0 warp detects + resets + releases.
__device__ __forceinline__ void grid_sync(unsigned& barI, unsigned gen0) {
    barI++;
    __syncthreads();
    const int tid = threadIdx.x, bid = blockIdx.x;
    if (tid == 0) { __threadfence(); atomicAdd(&g_cnt2[(bid & 31) * 32], 1u); }
    if (bid == 0 && tid < 32) {
        unsigned nj = (tid < 20) ? 5u : 4u;
        volatile unsigned* c = &g_cnt2[tid * 32];
        while (*c < nj) __nanosleep(32);
        atomicSub(&g_cnt2[tid * 32], nj);
        __syncwarp(0xffffffffu);
        if (tid == 0) { __threadfence(); g_bar_gen = gen0 + barI; }
    } else if (tid == 0) {
        while ((unsigned)(g_bar_gen - gen0) < barI) __nanosleep(32);
    }
    __threadfence();
    __syncthreads();
}

// ---------------- LSTM: warp-autonomous 3-deep pipelined GEMM + fused cell ----------
// 128 blocks; block: 8 h-units (32 gate-rows) x 32 batch. 16 warps = 16 k-slices.
template <int MODE>
__device__ void lstm_phase(int t,
                           const float* __restrict__ Wih, const float* __restrict__ Whh,
                           const float* __restrict__ bih, const float* __restrict__ bhh,
                           float* dsm) {
    constexpr int K1 = (MODE == 0) ? C_ : H_;
    constexpr int K = K1 + H_;
    constexpr int KG = K / NGRP;     // 96 or 128
    constexpr int NCH = KG / CHK;    // 6 or 8
    const int bid = blockIdx.x, tid = threadIdx.x;
    if (bid >= 128) return;
    const float* __restrict__ X1 = (MODE == 0) ? g_YT : g_h1T[(t + 1) & 1];
    const float* __restrict__ X2 = (MODE == 0) ? g_h1T[t & 1] : g_h2T[t & 1];

    const int h0 = bid * 8;
    const int g = tid >> 5;          // warp = k-group 0..15
    const int lane = tid & 31;
    const int tx = lane & 7;         // batch quad: b = tx*4 .. tx*4+3
    const int trow = lane >> 3;      // rows trow + 4*i, i=0..7

    unsigned long long acc[8][2];
#pragma unroll
    for (int i = 0; i < 8; i++) { acc[i][0] = 0ull; acc[i][1] = 0ull; }

    auto load_chunk = [&](int c) {
        float* Xp = dsm + (c % NBUF) * (NGRP * GRPSZ) + g * GRPSZ;
        float* Wp = Xp + XSZ;
        const int kbase = g * KG + c * CHK;
#pragma unroll
        for (int i = 0; i < 4; i++) {               // X: [16 k][32 b]
            int f = lane + 32 * i;
            int kk = f >> 3, bq = f & 7;
            int kg2 = kbase + kk;
            const float* src = (kg2 < K1) ? (X1 + kg2 * B_ + bq * 4)
                                          : (X2 + (kg2 - K1) * B_ + bq * 4);
            cp16(Xp + kk * XSTR + bq * 4, src);
        }
#pragma unroll
        for (int i = 0; i < 4; i++) {               // W: [32 rows][16 k]
            int f = lane + 32 * i;
            int row = f >> 2, kq = f & 3;
            int kg2 = kbase + kq * 4;
            int grow = (row >> 3) * H_ + h0 + (row & 7);
            const float* src = (kg2 < K1) ? (Wih + (size_t)grow * K1 + kg2)
                                          : (Whh + (size_t)grow * H_ + (kg2 - K1));
            cp16(Wp + row * WSTR + kq * 4, src);
        }
    };

    load_chunk(0); cp_commit();
    load_chunk(1); cp_commit();

    for (int c = 0; c < NCH; c++) {
        if (c + 2 < NCH)      { load_chunk(c + 2); cp_commit(); cp_wait2(); }
        else if (c + 1 < NCH) { cp_wait1(); }
        else                  { cp_wait0(); }

        const float* Xp = dsm + (c % NBUF) * (NGRP * GRPSZ) + g * GRPSZ;
        const float* Wp = Xp + XSZ;
#pragma unroll
        for (int kk = 0; kk < CHK; kk += 4) {
            float4 wq[8];
            ulonglong2 xq[4];
#pragma unroll
            for (int i = 0; i < 8; i++)
                wq[i] = *(const float4*)&Wp[(trow + 4 * i) * WSTR + kk];
#pragma unroll
            for (int r = 0; r < 4; r++)
                xq[r] = *(const ulonglong2*)&Xp[(kk + r) * XSTR + tx * 4];
#pragma unroll
            for (int r = 0; r < 4; r++) {
#pragma unroll
                for (int i = 0; i < 8; i++) {
                    unsigned long long w2 = splat2(((const float*)&wq[i])[r]);
                    acc[i][0] = fma2(w2, xq[r].x, acc[i][0]);
                    acc[i][1] = fma2(w2, xq[r].y, acc[i][1]);
                }
            }
        }
    }

    // all warps done with buffers -> alias Gs over them
    __syncthreads();
    float* Gs = dsm;  // [16 g][32 rows][32 b]
#pragma unroll
    for (int i = 0; i < 8; i++) {
        ulonglong2 uv; uv.x = acc[i][0]; uv.y = acc[i][1];
        *(ulonglong2*)&Gs[g * 1024 + (trow + 4 * i) * 32 + tx * 4] = uv;
    }
    __syncthreads();

    if (tid < 256) {
        int u = tid >> 5, b = tid & 31;
        float gate[4];
#pragma unroll
        for (int q = 0; q < 4; q++) {
            int l = q * 8 + u;
            int row = q * H_ + h0 + u;
            float s = bih[row] + bhh[row];
#pragma unroll
            for (int gg = 0; gg < NGRP; gg++) s += Gs[gg * 1024 + l * 32 + b];
            gate[q] = s;
        }
        float i_ = sigm(gate[0]), f_ = sigm(gate[1]), gv = ftanh(gate[2]), o_ = sigm(gate[3]);
        float* cS = (MODE == 0) ? g_c1 : g_c2;
        int hb = (h0 + u) * B_ + b;
        float cn = f_ * cS[hb] + i_ * gv;
        float hn = o_ * ftanh(cn);
        cS[hb] = cn;
        if (MODE == 0) {
            g_h1T[(t + 1) & 1][hb] = hn;
        } else {
            g_h2T[(t + 1) & 1][hb] = hn;
            g_h2n[b * H_ + h0 + u] = hn;
            g_h2hist[(size_t)t * H_ * B_ + hb] = hn;
        }
    }
    __syncthreads();
}

// ---------------- the single persistent kernel ----------------
__global__ void __launch_bounds__(NTHR, 1)
stdec_kernel(const float* __restrict__ videos,
             const float* __restrict__ h1in, const float* __restrict__ c1in,
             const float* __restrict__ h2in, const float* __restrict__ c2in,
             const float* __restrict__ spatialBias, const float* __restrict__ temporalBias,
             const float* __restrict__ W_h2p, const float* __restrict__ b_h2p,
             const float* __restrict__ W_sC21, const float* __restrict__ b_sC21,
             const float* __restrict__ W_h21, const float* __restrict__ b_h21,
             const float* __restrict__ W_tC21, const float* __restrict__ b_tC21,
             const float* __restrict__ Wih1, const float* __restrict__ Whh1,
             const float* __restrict__ bih1, const float* __restrict__ bhh1,
             const float* __restrict__ Wih2, const float* __restrict__ Whh2,
             const float* __restrict__ bih2, const float* __restrict__ bhh2,
             const float* __restrict__ W_fc, const float* __restrict__ b_fc,
             float* __restrict__ logits_out, float* __restrict__ alphas_out,
             float* __restrict__ betasT_out) {
    extern __shared__ __align__(16) float dsm[];
    const int bid = blockIdx.x, tid = threadIdx.x;
    const int lane = tid & 31, wid = tid >> 5;
    const int gw = bid * NWRP + wid;

    unsigned barI = 0;
    unsigned gen0 = g_bar_gen;

    // ---- init states ----
    for (int idx = bid * NTHR + tid; idx < H_ * B_; idx += NBLK * NTHR) {
        int h = idx >> 5, b = idx & 31;
        g_h1T[0][idx] = h1in[h];
        g_h2T[0][idx] = h2in[h];
        g_c1[idx] = c1in[h];
        g_c2[idx] = c2in[h];
        g_h2n[b * H_ + h] = h2in[h];
    }

    // ---- precompute sA2pre / tC2pre (2 tasks per block) ----
    {
        float* ws = dsm;
        float* wt = dsm + C_;
        for (int i = tid; i < C_; i += NTHR) { ws[i] = W_sC21[i]; wt[i] = W_tC21[i]; }
        __syncthreads();
        float bs0 = b_sC21[0];
        int half = tid >> 8, p = tid & 255;
        for (int task = bid * 2 + half; task < B_ * T_; task += NBLK * 2) {
            int b = task / T_, t = task % T_;
            if (p < P_) {
                const float* vp = videos + ((size_t)(b * T_ + t) * C_) * P_ + p;
                float accs = 0.f, acct = 0.f;
#pragma unroll 8
                for (int c = 0; c < C_; c++) {
                    float v = vp[(size_t)c * P_];
                    accs += v * ws[c];
                    acct += v * wt[c];
                }
                int o = (t * B_ + b) * P_ + p;
                g_sA2pre[o] = accs + bs0 + spatialBias[p];
                g_tC2pre[o] = acct;
            }
        }
        __syncthreads();
    }
    grid_sync(barI, gen0);

    // ---- recurrence: 4 phases / 4 barriers per step ----
    for (int t = 0; t < T_; t++) {
        // phase 1: scores, warp per (b,p) dot over all blocks; p==196 -> betaH
        for (int task = gw; task < B_ * 197; task += NBLK * NWRP) {
            int b = task / 197, p = task % 197;
            const float4* xr = (const float4*)(g_h2n + b * H_);
            const float4* wr = (const float4*)((p < P_) ? (W_h2p + (size_t)p * H_) : W_h21);
            float acc = 0.f;
#pragma unroll
            for (int j = 0; j < 8; j++) acc += d4(wr[lane + 32 * j], xr[lane + 32 * j]);
            for (int o = 16; o; o >>= 1) acc += __shfl_xor_sync(~0u, acc, o);
            if (lane == 0) {
                if (p < P_)
                    g_sc[b * P_ + p] = acc + b_h2p[p] + g_sA2pre[(t * B_ + b) * P_ + p];
                else
                    g_betaH[b] = acc;
            }
        }
        grid_sync(barI, gen0);

        // phase 2: softmax + alpha/beta out + Y (blocks 0..127: b = bid>>2, chunk = bid&3)
        if (bid < 128) {
            float* sred = dsm;          // [16]
            float* s_alpha = dsm + 16;  // [196]
            int b = bid >> 2, chunk = bid & 3, c0 = chunk * 128;

            float v = (tid < P_) ? g_sc[b * P_ + tid] : -1e30f;
            float m = v;
            for (int o = 16; o; o >>= 1) m = fmaxf(m, __shfl_xor_sync(~0u, m, o));
            if (lane == 0) sred[wid] = m;
            __syncthreads();
            float mAll = sred[0];
#pragma unroll
            for (int i = 1; i < NWRP; i++) mAll = fmaxf(mAll, sred[i]);
            float e = (tid < P_) ? __expf(v - mAll) : 0.f;
            float s = e;
            for (int o = 16; o; o >>= 1) s += __shfl_xor_sync(~0u, s, o);
            __syncthreads();
            if (lane == 0) sred[wid] = s;
            __syncthreads();
            float sAll = sred[0];
#pragma unroll
            for (int i = 1; i < NWRP; i++) sAll += sred[i];
            float a = e / sAll;
            __syncthreads();
            if (tid < P_) {
                s_alpha[tid] = a;
                if (chunk == 0) alphas_out[((size_t)t * B_ + b) * P_ + tid] = a;
            }
            __syncthreads();

            if (chunk == 0) {
                float acc = (tid < P_) ? a * g_tC2pre[(t * B_ + b) * P_ + tid] : 0.f;
                for (int o = 16; o; o >>= 1) acc += __shfl_xor_sync(~0u, acc, o);
                if (lane == 0) sred[wid] = acc;
                __syncthreads();
                if (tid == 0) {
                    float sum = 0.f;
#pragma unroll
                    for (int i = 0; i < NWRP; i++) sum += sred[i];
                    g_beta[t * B_ + b] = sum + g_betaH[b] + b_h21[0] + b_tC21[0] + temporalBias[0];
                }
            }

            // Y: warp per c-row within this block's 128-c chunk
            for (int c = wid; c < 128; c += NWRP) {
                int cg = c0 + c;
                const float* vp = videos + (((size_t)b * T_ + t) * C_ + cg) * P_;
                float acc = 0.f;
                for (int p = lane; p < P_; p += 32) acc += s_alpha[p] * vp[p];
                for (int o = 16; o; o >>= 1) acc += __shfl_xor_sync(~0u, acc, o);
                if (lane == 0) g_YT[cg * B_ + b] = acc;
            }
        }
        grid_sync(barI, gen0);

        lstm_phase<0>(t, Wih1, Whh1, bih1, bhh1, dsm);
        grid_sync(barI, gen0);
        lstm_phase<1>(t, Wih2, Whh2, bih2, bhh2, dsm);
        grid_sync(barI, gen0);
    }

    // ---- betas softmax over time ----
    if (bid == 0 && tid < B_) {
        int b = tid;
        float v[T_];
        float m = -1e30f;
#pragma unroll
        for (int t = 0; t < T_; t++) { v[t] = g_beta[t * B_ + b]; m = fmaxf(m, v[t]); }
        float s = 0.f;
#pragma unroll
        for (int t = 0; t < T_; t++) { v[t] = __expf(v[t] - m); s += v[t]; }
        float inv = 1.f / s;
#pragma unroll
        for (int t = 0; t < T_; t++) {
            float bt = v[t] * inv;
            g_betasT[b * T_ + t] = bt;
            betasT_out[b * T_ + t] = bt;
        }
    }
    grid_sync(barI, gen0);

    // ---- hbar[b][h] = sum_t betasT[b][t] * h2hist[t][h][b] ----
    for (int idx = bid * NTHR + tid; idx < H_ * B_; idx += NBLK * NTHR) {
        int h = idx >> 5, b = idx & 31;
        float acc = 0.f;
#pragma unroll
        for (int t = 0; t < T_; t++)
            acc += g_betasT[b * T_ + t] * g_h2hist[(size_t)t * H_ * B_ + h * B_ + b];
        g_hbarN[b * H_ + h] = acc;
    }
    grid_sync(barI, gen0);

    // ---- logits: warp per (nc,b) dot over H ----
    for (int task = gw; task < NC_ * B_; task += NBLK * NWRP) {
        int nc = task / B_, b = task % B_;
        const float4* wr = (const float4*)(W_fc + (size_t)nc * H_);
        const float4* xr = (const float4*)(g_hbarN + (size_t)b * H_);
        float acc = 0.f;
#pragma unroll
        for (int j = 0; j < 8; j++) acc += d4(wr[lane + 32 * j], xr[lane + 32 * j]);
        for (int o = 16; o; o >>= 1) acc += __shfl_xor_sync(~0u, acc, o);
        if (lane == 0) logits_out[b * NC_ + nc] = acc + b_fc[nc];
    }
}

// ---------------- launch ----------------
extern "C" void kernel_launch(void* const* d_in, const int* in_sizes, int n_in,
                              void* d_out, int out_size) {
    const float* videos       = (const float*)d_in[0];
    const float* h1           = (const float*)d_in[1];
    const float* c1           = (const float*)d_in[2];
    const float* h2           = (const float*)d_in[3];
    const float* c2           = (const float*)d_in[4];
    const float* spatialBias  = (const float*)d_in[5];
    const float* temporalBias = (const float*)d_in[6];
    const float* W_h2p        = (const float*)d_in[7];
    const float* b_h2p        = (const float*)d_in[8];
    const float* W_sC21       = (const float*)d_in[9];
    const float* b_sC21       = (const float*)d_in[10];
    const float* W_h21        = (const float*)d_in[11];
    const float* b_h21        = (const float*)d_in[12];
    const float* W_tC21       = (const float*)d_in[13];
    const float* b_tC21       = (const float*)d_in[14];
    const float* Wih1         = (const float*)d_in[15];
    const float* Whh1         = (const float*)d_in[16];
    const float* bih1         = (const float*)d_in[17];
    const float* bhh1         = (const float*)d_in[18];
    const float* Wih2         = (const float*)d_in[19];
    const float* Whh2         = (const float*)d_in[20];
    const float* bih2         = (const float*)d_in[21];
    const float* bhh2         = (const float*)d_in[22];
    const float* W_fc         = (const float*)d_in[23];
    const float* b_fc         = (const float*)d_in[24];

    float* out        = (float*)d_out;
    float* logits_out = out;
    float* alphas_out = out + B_ * NC_;
    float* betasT_out = out + B_ * NC_ + (size_t)T_ * B_ * P_;

    cudaFuncSetAttribute(stdec_kernel, cudaFuncAttributeMaxDynamicSharedMemorySize, SMEM_BYTES);
    stdec_kernel<<<NBLK, NTHR, SMEM_BYTES>>>(videos, h1, c1, h2, c2, spatialBias, temporalBias,
                                 W_h2p, b_h2p, W_sC21, b_sC21, W_h21, b_h21, W_tC21, b_tC21,
                                 Wih1, Whh1, bih1, bhh1, Wih2, Whh2, bih2, bhh2,
                                 W_fc, b_fc, logits_out, alphas_out, betasT_out);
}